// round 1
// baseline (speedup 1.0000x reference)
#include <cuda_runtime.h>
#include <math.h>

#define N 8192
#define D 128
#define TILE 128
#define KC 32
#define NB (N / TILE)
#define WEIGHT 0.01f

// Scratch (device globals: no allocation allowed in kernel_launch)
__device__ float g_f[N * D];     // normalized rows
__device__ float g_suffix[N];    // suffix[r] = sum_{j>=r+1} exp(sim[r][j])
__device__ float g_prefix[N];    // prefix[a] = sum_{b<=a-2} exp(sim[a][b])
__device__ float g_pos[N];       // pos[r]    = sim[r][r+1]

// ---------------------------------------------------------------------------
// Kernel 1: L2-normalize rows (one warp per row) + zero the accumulators.
// ---------------------------------------------------------------------------
__global__ void normalize_kernel(const float* __restrict__ in) {
    int gw   = (blockIdx.x * blockDim.x + threadIdx.x) >> 5;  // global warp = row
    int lane = threadIdx.x & 31;
    if (gw >= N) return;
    float4 v = ((const float4*)(in + (size_t)gw * D))[lane];  // 32 lanes x 4 = 128
    float ss = v.x * v.x + v.y * v.y + v.z * v.z + v.w * v.w;
#pragma unroll
    for (int o = 16; o > 0; o >>= 1) ss += __shfl_xor_sync(0xffffffffu, ss, o);
    float scale = 1.0f / fmaxf(sqrtf(ss), 1e-12f);
    float4 o4 = make_float4(v.x * scale, v.y * scale, v.z * scale, v.w * scale);
    ((float4*)(g_f + (size_t)gw * D))[lane] = o4;
    if (lane == 0) { g_suffix[gw] = 0.0f; g_prefix[gw] = 0.0f; }
}

// ---------------------------------------------------------------------------
// Kernel 2: upper-triangle gram tiles, fused exp + row/col reductions.
// Block = 256 threads, tile 128x128, 8x8 per-thread register blocking.
// ---------------------------------------------------------------------------
__global__ __launch_bounds__(256) void gram_kernel() {
    const int I = blockIdx.y;
    const int J = blockIdx.x;
    if (J < I) return;  // upper triangle only

    __shared__ float As[KC][TILE + 4];       // [k][row], padded
    __shared__ float Bs[KC][TILE + 4];
    __shared__ float colPart[16][TILE];      // staging for column reduction

    const int t  = threadIdx.x;
    const int rg = t >> 4;                   // 0..15 row-group
    const int cg = t & 15;                   // 0..15 col-group
    const int r0 = rg * 8;
    const int c0 = cg * 8;

    const float* __restrict__ Ab = g_f + (size_t)I * TILE * D;
    const float* __restrict__ Bb = g_f + (size_t)J * TILE * D;

    float acc[8][8];
#pragma unroll
    for (int i = 0; i < 8; i++)
#pragma unroll
        for (int j = 0; j < 8; j++) acc[i][j] = 0.0f;

    for (int k0 = 0; k0 < D; k0 += KC) {
        // Load 128x32 chunks of A and B, transposed to [k][row] in smem.
#pragma unroll
        for (int it = 0; it < 4; it++) {
            int idx = t + it * 256;          // 0..1023
            int row = idx >> 3;
            int kq  = idx & 7;
            float4 va = *(const float4*)(Ab + row * D + k0 + kq * 4);
            As[kq * 4 + 0][row] = va.x; As[kq * 4 + 1][row] = va.y;
            As[kq * 4 + 2][row] = va.z; As[kq * 4 + 3][row] = va.w;
            float4 vb = *(const float4*)(Bb + row * D + k0 + kq * 4);
            Bs[kq * 4 + 0][row] = vb.x; Bs[kq * 4 + 1][row] = vb.y;
            Bs[kq * 4 + 2][row] = vb.z; Bs[kq * 4 + 3][row] = vb.w;
        }
        __syncthreads();

#pragma unroll
        for (int k = 0; k < KC; k++) {
            float a[8], b[8];
            *(float4*)(a)     = *(const float4*)&As[k][r0];
            *(float4*)(a + 4) = *(const float4*)&As[k][r0 + 4];
            *(float4*)(b)     = *(const float4*)&Bs[k][c0];
            *(float4*)(b + 4) = *(const float4*)&Bs[k][c0 + 4];
#pragma unroll
            for (int i = 0; i < 8; i++)
#pragma unroll
                for (int j = 0; j < 8; j++)
                    acc[i][j] = fmaf(a[i], b[j], acc[i][j]);
        }
        __syncthreads();
    }

    // --- Epilogue: exp + masked accumulation ---
    const int gi0 = I * TILE + r0;
    const int gj0 = J * TILE + c0;
    float rpart[8], cpart[8];
#pragma unroll
    for (int i = 0; i < 8; i++) { rpart[i] = 0.0f; cpart[i] = 0.0f; }

#pragma unroll
    for (int i = 0; i < 8; i++) {
        int gi = gi0 + i;
#pragma unroll
        for (int j = 0; j < 8; j++) {
            int gj = gj0 + j;
            if (gj > gi) {
                float s = acc[i][j];
                float e = __expf(s);
                rpart[i] += e;                 // suffix[gi]: all j >= gi+1
                if (gj >= gi + 2) cpart[j] += e;   // prefix[gj]: cols <= gj-2
                else              g_pos[gi] = s;   // gj == gi+1 (unique writer)
            }
        }
    }

    // Row reduction: sum across the 16 lanes sharing this rg (half-warp bfly).
#pragma unroll
    for (int i = 0; i < 8; i++) {
#pragma unroll
        for (int o = 8; o > 0; o >>= 1)
            rpart[i] += __shfl_xor_sync(0xffffffffu, rpart[i], o);
    }
    if ((t & 15) == 0) {
#pragma unroll
        for (int i = 0; i < 8; i++)
            atomicAdd(&g_suffix[gi0 + i], rpart[i]);
    }

    // Column reduction: stage per-row-group partials, then sum across groups.
#pragma unroll
    for (int j = 0; j < 8; j++) colPart[rg][c0 + j] = cpart[j];
    __syncthreads();
    if (t < TILE) {
        float s = 0.0f;
#pragma unroll
        for (int g = 0; g < 16; g++) s += colPart[g][t];
        atomicAdd(&g_prefix[J * TILE + t], s);
    }
}

// ---------------------------------------------------------------------------
// Kernel 3: per-row logsumexp combine + final scalar reduction.
// ---------------------------------------------------------------------------
__global__ void finish_kernel(float* __restrict__ out) {
    __shared__ float red[256];
    int t = threadIdx.x;
    float local = 0.0f;
    for (int r = t; r < N - 1; r += 256) {
        float lse = logf(g_suffix[r] + g_prefix[r + 1]);
        local += lse - g_pos[r];
    }
    red[t] = local;
    __syncthreads();
    for (int s = 128; s > 0; s >>= 1) {
        if (t < s) red[t] += red[t + s];
        __syncthreads();
    }
    if (t == 0) out[0] = -WEIGHT * (red[0] / (float)N);
}

// ---------------------------------------------------------------------------
extern "C" void kernel_launch(void* const* d_in, const int* in_sizes, int n_in,
                              void* d_out, int out_size) {
    const float* factor = (const float*)d_in[0];
    (void)in_sizes; (void)n_in; (void)out_size;

    normalize_kernel<<<(N * 32) / 256, 256>>>(factor);

    dim3 grid(NB, NB);
    gram_kernel<<<grid, 256>>>();

    finish_kernel<<<1, 256>>>((float*)d_out);
}

// round 4
// speedup vs baseline: 5.3322x; 5.3322x over previous
#include <cuda_runtime.h>
#include <cuda_fp16.h>
#include <cstdint>
#include <stdint.h>
#include <math.h>

#define N 8192
#define D 128
#define TILE 128
#define NB (N / TILE)          // 64
#define NTRI (NB * (NB + 1) / 2)  // 2080 upper-tri tiles
#define LDH 136                // padded SMEM stride in halfs (272B, conflict-free)
#define WEIGHT 0.01f

// ---------------------------------------------------------------------------
// Device scratch (no allocation allowed in kernel_launch)
// ---------------------------------------------------------------------------
__device__ float  g_f[N * D];     // normalized rows, fp32 (exact pos)
__device__ __half g_fh[N * D];    // normalized rows, fp16 (MMA operands)
__device__ float  g_suffix[N];    // suffix[r] = sum_{j>=r+1} exp(sim[r][j])
__device__ float  g_prefix[N];    // prefix[a] = sum_{b<=a-2} exp(sim[a][b])
__device__ float  g_pos[N];       // pos[r]    = sim[r][r+1] (exact fp32)

// ---------------------------------------------------------------------------
__device__ __forceinline__ void mma16816(float* c,
    uint32_t a0, uint32_t a1, uint32_t a2, uint32_t a3,
    uint32_t b0, uint32_t b1)
{
    asm volatile(
        "mma.sync.aligned.m16n8k16.row.col.f32.f16.f16.f32 "
        "{%0,%1,%2,%3}, {%4,%5,%6,%7}, {%8,%9}, {%0,%1,%2,%3};"
        : "+f"(c[0]), "+f"(c[1]), "+f"(c[2]), "+f"(c[3])
        : "r"(a0), "r"(a1), "r"(a2), "r"(a3), "r"(b0), "r"(b1));
}

// ---------------------------------------------------------------------------
// Kernel 1: L2-normalize rows -> fp32 + fp16 copies; zero accumulators.
// ---------------------------------------------------------------------------
__global__ void normalize_kernel(const float* __restrict__ in) {
    int gw   = (blockIdx.x * blockDim.x + threadIdx.x) >> 5;
    int lane = threadIdx.x & 31;
    if (gw >= N) return;
    float4 v = ((const float4*)(in + (size_t)gw * D))[lane];
    float ss = v.x * v.x + v.y * v.y + v.z * v.z + v.w * v.w;
#pragma unroll
    for (int o = 16; o > 0; o >>= 1) ss += __shfl_xor_sync(0xffffffffu, ss, o);
    float scale = 1.0f / fmaxf(sqrtf(ss), 1e-12f);
    float4 o4 = make_float4(v.x * scale, v.y * scale, v.z * scale, v.w * scale);
    ((float4*)(g_f + (size_t)gw * D))[lane] = o4;
    __half2 h0 = __floats2half2_rn(o4.x, o4.y);
    __half2 h1 = __floats2half2_rn(o4.z, o4.w);
    ((__half2*)(g_fh + (size_t)gw * D))[lane * 2 + 0] = h0;
    ((__half2*)(g_fh + (size_t)gw * D))[lane * 2 + 1] = h1;
    if (lane == 0) { g_suffix[gw] = 0.0f; g_prefix[gw] = 0.0f; }
}

// ---------------------------------------------------------------------------
// Kernel 2: exact fp32 pos[r] = <f_r, f_{r+1}>, one warp per r.
// ---------------------------------------------------------------------------
__global__ void pos_kernel() {
    int gw   = (blockIdx.x * blockDim.x + threadIdx.x) >> 5;
    int lane = threadIdx.x & 31;
    if (gw >= N - 1) return;
    float4 a = ((const float4*)(g_f + (size_t)gw * D))[lane];
    float4 b = ((const float4*)(g_f + (size_t)(gw + 1) * D))[lane];
    float d = a.x * b.x + a.y * b.y + a.z * b.z + a.w * b.w;
#pragma unroll
    for (int o = 16; o > 0; o >>= 1) d += __shfl_xor_sync(0xffffffffu, d, o);
    if (lane == 0) g_pos[gw] = d;
}

// ---------------------------------------------------------------------------
// Kernel 3: gram tiles via mma.sync (HMMA), fused exp + reductions.
// 256 threads = 8 warps (2x4); warp computes 64x32; thread: 4x4 m16n8k16.
// ---------------------------------------------------------------------------
#define SMEM_BYTES (2 * TILE * LDH * 2 + 2 * TILE * 4)  // As+Bs + s_row+s_col

__global__ __launch_bounds__(256, 2) void gram_mma_kernel() {
    // Triangular block index -> (I, J), J >= I
    int t = blockIdx.x;
    int I = (int)((2.0f * NB + 1.0f -
                   sqrtf((2.0f * NB + 1.0f) * (2.0f * NB + 1.0f) - 8.0f * (float)t)) * 0.5f);
    while (I > 0 && t < I * NB - I * (I - 1) / 2) --I;
    while (t >= (I + 1) * NB - (I + 1) * I / 2) ++I;
    const int J = I + (t - (I * NB - I * (I - 1) / 2));

    extern __shared__ char smem[];
    __half* As    = (__half*)smem;                     // [128][LDH]
    __half* Bs    = As + TILE * LDH;                   // [128][LDH]
    float*  s_row = (float*)(Bs + TILE * LDH);         // [128]
    float*  s_col = s_row + TILE;                      // [128]

    const int tid  = threadIdx.x;
    const int wid  = tid >> 5;
    const int lane = tid & 31;
    const int wrow = wid >> 2;        // 0..1 -> 64-row half
    const int wcol = wid & 3;         // 0..3 -> 32-col quarter
    const int g    = lane >> 2;       // 0..7
    const int tg   = lane & 3;        // 0..3

    if (tid < TILE) s_row[tid] = 0.0f;
    else            s_col[tid - TILE] = 0.0f;

    // Stage A (rows of block I) and B (rows of block J) into padded SMEM.
    const __half* __restrict__ Ag = g_fh + (size_t)I * TILE * D;
    const __half* __restrict__ Bg = g_fh + (size_t)J * TILE * D;
#pragma unroll
    for (int it = 0; it < 8; it++) {
        int idx = tid + it * 256;     // 0..2047
        int row = idx >> 4;
        int ch  = idx & 15;           // 16B chunk (8 halfs)
        *(float4*)(As + row * LDH + ch * 8) = *(const float4*)(Ag + row * D + ch * 8);
        *(float4*)(Bs + row * LDH + ch * 8) = *(const float4*)(Bg + row * D + ch * 8);
    }
    __syncthreads();

    float acc[4][4][4];
#pragma unroll
    for (int mt = 0; mt < 4; mt++)
#pragma unroll
        for (int nt = 0; nt < 4; nt++)
#pragma unroll
            for (int e = 0; e < 4; e++) acc[mt][nt][e] = 0.0f;

#pragma unroll
    for (int k0 = 0; k0 < D; k0 += 16) {
        uint32_t bfr[4][2];
#pragma unroll
        for (int nt = 0; nt < 4; nt++) {
            const __half* bp = Bs + (wcol * 32 + nt * 8 + g) * LDH + k0 + tg * 2;
            bfr[nt][0] = *(const uint32_t*)bp;
            bfr[nt][1] = *(const uint32_t*)(bp + 8);
        }
#pragma unroll
        for (int mt = 0; mt < 4; mt++) {
            const __half* ap = As + (wrow * 64 + mt * 16 + g) * LDH + k0 + tg * 2;
            uint32_t a0 = *(const uint32_t*)ap;
            uint32_t a1 = *(const uint32_t*)(ap + 8 * LDH);
            uint32_t a2 = *(const uint32_t*)(ap + 8);
            uint32_t a3 = *(const uint32_t*)(ap + 8 * LDH + 8);
#pragma unroll
            for (int nt = 0; nt < 4; nt++)
                mma16816(acc[mt][nt], a0, a1, a2, a3, bfr[nt][0], bfr[nt][1]);
        }
    }

    // --- Epilogue: masked exp + row/col reductions ---
    float csum[4][2];
#pragma unroll
    for (int nt = 0; nt < 4; nt++) { csum[nt][0] = 0.0f; csum[nt][1] = 0.0f; }

#pragma unroll
    for (int mt = 0; mt < 4; mt++) {
        const int gi0 = I * TILE + wrow * 64 + mt * 16 + g;
        const int gi1 = gi0 + 8;
        float rs0 = 0.0f, rs1 = 0.0f;
#pragma unroll
        for (int nt = 0; nt < 4; nt++) {
            const int gj0 = J * TILE + wcol * 32 + nt * 8 + tg * 2;
            const int gj1 = gj0 + 1;
            float e00 = (gj0 > gi0) ? __expf(acc[mt][nt][0]) : 0.0f;
            float e01 = (gj1 > gi0) ? __expf(acc[mt][nt][1]) : 0.0f;
            float e10 = (gj0 > gi1) ? __expf(acc[mt][nt][2]) : 0.0f;
            float e11 = (gj1 > gi1) ? __expf(acc[mt][nt][3]) : 0.0f;
            rs0 += e00 + e01;
            rs1 += e10 + e11;
            csum[nt][0] += ((gj0 >= gi0 + 2) ? e00 : 0.0f) + ((gj0 >= gi1 + 2) ? e10 : 0.0f);
            csum[nt][1] += ((gj1 >= gi0 + 2) ? e01 : 0.0f) + ((gj1 >= gi1 + 2) ? e11 : 0.0f);
        }
        // reduce row sums across tg lanes (bits 0-1)
        rs0 += __shfl_xor_sync(0xffffffffu, rs0, 1);
        rs0 += __shfl_xor_sync(0xffffffffu, rs0, 2);
        rs1 += __shfl_xor_sync(0xffffffffu, rs1, 1);
        rs1 += __shfl_xor_sync(0xffffffffu, rs1, 2);
        if (tg == 0) {
            atomicAdd(&s_row[wrow * 64 + mt * 16 + g], rs0);
            atomicAdd(&s_row[wrow * 64 + mt * 16 + g + 8], rs1);
        }
    }

    // reduce col sums across g lanes (bits 2-4)
#pragma unroll
    for (int nt = 0; nt < 4; nt++) {
#pragma unroll
        for (int e = 0; e < 2; e++) {
            float v = csum[nt][e];
            v += __shfl_xor_sync(0xffffffffu, v, 4);
            v += __shfl_xor_sync(0xffffffffu, v, 8);
            v += __shfl_xor_sync(0xffffffffu, v, 16);
            if (g == 0) atomicAdd(&s_col[wcol * 32 + nt * 8 + tg * 2 + e], v);
        }
    }

    __syncthreads();
    if (tid < TILE) atomicAdd(&g_suffix[I * TILE + tid], s_row[tid]);
    else            atomicAdd(&g_prefix[J * TILE + tid - TILE], s_col[tid - TILE]);
}

// ---------------------------------------------------------------------------
// Kernel 4: per-row logsumexp combine + final scalar reduction.
// ---------------------------------------------------------------------------
__global__ void finish_kernel(float* __restrict__ out) {
    __shared__ float red[256];
    int t = threadIdx.x;
    float local = 0.0f;
    for (int r = t; r < N - 1; r += 256) {
        float lse = logf(g_suffix[r] + g_prefix[r + 1]);
        local += lse - g_pos[r];
    }
    red[t] = local;
    __syncthreads();
    for (int s = 128; s > 0; s >>= 1) {
        if (t < s) red[t] += red[t + s];
        __syncthreads();
    }
    if (t == 0) out[0] = -WEIGHT * (red[0] / (float)N);
}

// ---------------------------------------------------------------------------
extern "C" void kernel_launch(void* const* d_in, const int* in_sizes, int n_in,
                              void* d_out, int out_size) {
    const float* factor = (const float*)d_in[0];
    (void)in_sizes; (void)n_in; (void)out_size;

    static bool attr_set = false;
    if (!attr_set) {
        cudaFuncSetAttribute(gram_mma_kernel,
                             cudaFuncAttributeMaxDynamicSharedMemorySize, SMEM_BYTES);
        attr_set = true;
    }

    normalize_kernel<<<(N * 32) / 256, 256>>>(factor);
    pos_kernel<<<(N * 32 + 255) / 256, 256>>>();
    gram_mma_kernel<<<NTRI, 256, SMEM_BYTES>>>();
    finish_kernel<<<1, 256>>>((float*)d_out);
}

// round 5
// speedup vs baseline: 5.8998x; 1.1064x over previous
#include <cuda_runtime.h>
#include <cuda_fp16.h>
#include <cstdint>
#include <stdint.h>
#include <math.h>

#define N 8192
#define D 128
#define TILE 128
#define NB (N / TILE)             // 64
#define NTRI (NB * (NB + 1) / 2)  // 2080 upper-tri tiles
#define NCTA 296                  // 148 SMs x 2 resident CTAs
#define LDH 136                   // padded SMEM stride in halfs, conflict-free
#define WEIGHT 0.01f

// ---------------------------------------------------------------------------
// Device scratch
// ---------------------------------------------------------------------------
__device__ float  g_f[N * D];     // normalized rows, fp32 (exact pos)
__device__ __half g_fh[N * D];    // normalized rows, fp16 (MMA operands)
__device__ float  g_suffix[N];
__device__ float  g_prefix[N];
__device__ float  g_pos[N];
__device__ float  g_partial[32];

// ---------------------------------------------------------------------------
__device__ __forceinline__ void mma16816(float* c,
    uint32_t a0, uint32_t a1, uint32_t a2, uint32_t a3,
    uint32_t b0, uint32_t b1)
{
    asm volatile(
        "mma.sync.aligned.m16n8k16.row.col.f32.f16.f16.f32 "
        "{%0,%1,%2,%3}, {%4,%5,%6,%7}, {%8,%9}, {%0,%1,%2,%3};"
        : "+f"(c[0]), "+f"(c[1]), "+f"(c[2]), "+f"(c[3])
        : "r"(a0), "r"(a1), "r"(a2), "r"(a3), "r"(b0), "r"(b1));
}

// ---------------------------------------------------------------------------
// Kernel 1: L2-normalize rows -> fp32 + fp16; zero accumulators.
// ---------------------------------------------------------------------------
__global__ void normalize_kernel(const float* __restrict__ in) {
    int gw   = (blockIdx.x * blockDim.x + threadIdx.x) >> 5;
    int lane = threadIdx.x & 31;
    if (gw >= N) return;
    float4 v = ((const float4*)(in + (size_t)gw * D))[lane];
    float ss = v.x * v.x + v.y * v.y + v.z * v.z + v.w * v.w;
#pragma unroll
    for (int o = 16; o > 0; o >>= 1) ss += __shfl_xor_sync(0xffffffffu, ss, o);
    float scale = 1.0f / fmaxf(sqrtf(ss), 1e-12f);
    float4 o4 = make_float4(v.x * scale, v.y * scale, v.z * scale, v.w * scale);
    ((float4*)(g_f + (size_t)gw * D))[lane] = o4;
    __half2 h0 = __floats2half2_rn(o4.x, o4.y);
    __half2 h1 = __floats2half2_rn(o4.z, o4.w);
    ((__half2*)(g_fh + (size_t)gw * D))[lane * 2 + 0] = h0;
    ((__half2*)(g_fh + (size_t)gw * D))[lane * 2 + 1] = h1;
    if (lane == 0) { g_suffix[gw] = 0.0f; g_prefix[gw] = 0.0f; }
}

// ---------------------------------------------------------------------------
// Kernel 2: exact fp32 pos[r] = <f_r, f_{r+1}>, one warp per r.
// ---------------------------------------------------------------------------
__global__ void pos_kernel() {
    int gw   = (blockIdx.x * blockDim.x + threadIdx.x) >> 5;
    int lane = threadIdx.x & 31;
    if (gw >= N - 1) return;
    float4 a = ((const float4*)(g_f + (size_t)gw * D))[lane];
    float4 b = ((const float4*)(g_f + (size_t)(gw + 1) * D))[lane];
    float d = a.x * b.x + a.y * b.y + a.z * b.z + a.w * b.w;
#pragma unroll
    for (int o = 16; o > 0; o >>= 1) d += __shfl_xor_sync(0xffffffffu, d, o);
    if (lane == 0) g_pos[gw] = d;
}

// ---------------------------------------------------------------------------
// Kernel 3: persistent gram. Each CTA processes a contiguous slice of the
// triangular tile list; A tile reloaded only when I changes.
// ---------------------------------------------------------------------------
#define SMEM_BYTES (2 * TILE * LDH * 2 + 2 * TILE * 4)

__global__ __launch_bounds__(256, 2) void gram_mma_kernel() {
    extern __shared__ char smem[];
    __half* As    = (__half*)smem;                  // [128][LDH]
    __half* Bs    = As + TILE * LDH;                // [128][LDH]
    float*  s_row = (float*)(Bs + TILE * LDH);      // [128]
    float*  s_col = s_row + TILE;                   // [128]

    const int tid  = threadIdx.x;
    const int wid  = tid >> 5;
    const int lane = tid & 31;
    const int wrow = wid >> 2;        // 0..1
    const int wcol = wid & 3;         // 0..3
    const int g    = lane >> 2;       // 0..7
    const int tg   = lane & 3;        // 0..3

    const int lo = (int)(((long long)blockIdx.x * NTRI) / NCTA);
    const int hi = (int)(((long long)(blockIdx.x + 1) * NTRI) / NCTA);

    int curI = -1;
    // Find I for tile lo: cum(I) = I*NB - I*(I-1)/2
    int I = 0;
    while ((I + 1) * NB - (I + 1) * I / 2 <= lo) ++I;

    for (int t = lo; t < hi; ++t) {
        while ((I + 1) * NB - (I + 1) * I / 2 <= t) ++I;
        const int J = I + (t - (I * NB - I * (I - 1) / 2));

        __syncthreads();   // prior tile's global-atomic reads of s_row/s_col done

        if (tid < TILE) s_row[tid] = 0.0f;
        else            s_col[tid - TILE] = 0.0f;

        const bool loadA = (I != curI);
        curI = I;
        const __half* __restrict__ Ag = g_fh + (size_t)I * TILE * D;
        const __half* __restrict__ Bg = g_fh + (size_t)J * TILE * D;
#pragma unroll
        for (int it = 0; it < 8; it++) {
            int idx = tid + it * 256;
            int row = idx >> 4;
            int ch  = idx & 15;
            if (loadA)
                *(float4*)(As + row * LDH + ch * 8) =
                    *(const float4*)(Ag + row * D + ch * 8);
            *(float4*)(Bs + row * LDH + ch * 8) =
                *(const float4*)(Bg + row * D + ch * 8);
        }
        __syncthreads();

        float acc[4][4][4];
#pragma unroll
        for (int mt = 0; mt < 4; mt++)
#pragma unroll
            for (int nt = 0; nt < 4; nt++)
#pragma unroll
                for (int e = 0; e < 4; e++) acc[mt][nt][e] = 0.0f;

#pragma unroll
        for (int k0 = 0; k0 < D; k0 += 16) {
            uint32_t bfr[4][2];
#pragma unroll
            for (int nt = 0; nt < 4; nt++) {
                const __half* bp = Bs + (wcol * 32 + nt * 8 + g) * LDH + k0 + tg * 2;
                bfr[nt][0] = *(const uint32_t*)bp;
                bfr[nt][1] = *(const uint32_t*)(bp + 8);
            }
#pragma unroll
            for (int mt = 0; mt < 4; mt++) {
                const __half* ap = As + (wrow * 64 + mt * 16 + g) * LDH + k0 + tg * 2;
                uint32_t a0 = *(const uint32_t*)ap;
                uint32_t a1 = *(const uint32_t*)(ap + 8 * LDH);
                uint32_t a2 = *(const uint32_t*)(ap + 8);
                uint32_t a3 = *(const uint32_t*)(ap + 8 * LDH + 8);
#pragma unroll
                for (int nt = 0; nt < 4; nt++)
                    mma16816(acc[mt][nt], a0, a1, a2, a3, bfr[nt][0], bfr[nt][1]);
            }
        }

        // --- Epilogue: masked exp + reductions ---
        float csum[4][2];
#pragma unroll
        for (int nt = 0; nt < 4; nt++) { csum[nt][0] = 0.0f; csum[nt][1] = 0.0f; }

#pragma unroll
        for (int mt = 0; mt < 4; mt++) {
            const int gi0 = I * TILE + wrow * 64 + mt * 16 + g;
            const int gi1 = gi0 + 8;
            float rs0 = 0.0f, rs1 = 0.0f;
#pragma unroll
            for (int nt = 0; nt < 4; nt++) {
                const int gj0 = J * TILE + wcol * 32 + nt * 8 + tg * 2;
                const int gj1 = gj0 + 1;
                float e00 = (gj0 > gi0) ? __expf(acc[mt][nt][0]) : 0.0f;
                float e01 = (gj1 > gi0) ? __expf(acc[mt][nt][1]) : 0.0f;
                float e10 = (gj0 > gi1) ? __expf(acc[mt][nt][2]) : 0.0f;
                float e11 = (gj1 > gi1) ? __expf(acc[mt][nt][3]) : 0.0f;
                rs0 += e00 + e01;
                rs1 += e10 + e11;
                csum[nt][0] += ((gj0 >= gi0 + 2) ? e00 : 0.0f) + ((gj0 >= gi1 + 2) ? e10 : 0.0f);
                csum[nt][1] += ((gj1 >= gi0 + 2) ? e01 : 0.0f) + ((gj1 >= gi1 + 2) ? e11 : 0.0f);
            }
            rs0 += __shfl_xor_sync(0xffffffffu, rs0, 1);
            rs0 += __shfl_xor_sync(0xffffffffu, rs0, 2);
            rs1 += __shfl_xor_sync(0xffffffffu, rs1, 1);
            rs1 += __shfl_xor_sync(0xffffffffu, rs1, 2);
            if (tg == 0) {
                atomicAdd(&s_row[wrow * 64 + mt * 16 + g], rs0);
                atomicAdd(&s_row[wrow * 64 + mt * 16 + g + 8], rs1);
            }
        }

#pragma unroll
        for (int nt = 0; nt < 4; nt++) {
#pragma unroll
            for (int e = 0; e < 2; e++) {
                float v = csum[nt][e];
                v += __shfl_xor_sync(0xffffffffu, v, 4);
                v += __shfl_xor_sync(0xffffffffu, v, 8);
                v += __shfl_xor_sync(0xffffffffu, v, 16);
                if (g == 0) atomicAdd(&s_col[wcol * 32 + nt * 8 + tg * 2 + e], v);
            }
        }

        __syncthreads();
        if (tid < TILE) atomicAdd(&g_suffix[I * TILE + tid], s_row[tid]);
        else            atomicAdd(&g_prefix[J * TILE + tid - TILE], s_col[tid - TILE]);
    }
}

// ---------------------------------------------------------------------------
// Kernel 4a: parallel partials of (lse - pos); 32 blocks x 256 threads.
// ---------------------------------------------------------------------------
__global__ void finish_partial_kernel() {
    __shared__ float red[256];
    int t = threadIdx.x;
    int r = blockIdx.x * 256 + t;
    float local = 0.0f;
    if (r < N - 1)
        local = logf(g_suffix[r] + g_prefix[r + 1]) - g_pos[r];
    red[t] = local;
    __syncthreads();
    for (int s = 128; s > 0; s >>= 1) {
        if (t < s) red[t] += red[t + s];
        __syncthreads();
    }
    if (t == 0) g_partial[blockIdx.x] = red[0];
}

// ---------------------------------------------------------------------------
// Kernel 4b: fold 32 partials -> scalar output.
// ---------------------------------------------------------------------------
__global__ void finish_final_kernel(float* __restrict__ out) {
    int t = threadIdx.x;   // 32 threads
    float v = g_partial[t];
#pragma unroll
    for (int o = 16; o > 0; o >>= 1) v += __shfl_xor_sync(0xffffffffu, v, o);
    if (t == 0) out[0] = -WEIGHT * (v / (float)N);
}

// ---------------------------------------------------------------------------
extern "C" void kernel_launch(void* const* d_in, const int* in_sizes, int n_in,
                              void* d_out, int out_size) {
    const float* factor = (const float*)d_in[0];
    (void)in_sizes; (void)n_in; (void)out_size;

    static bool attr_set = false;
    if (!attr_set) {
        cudaFuncSetAttribute(gram_mma_kernel,
                             cudaFuncAttributeMaxDynamicSharedMemorySize, SMEM_BYTES);
        attr_set = true;
    }

    normalize_kernel<<<(N * 32) / 256, 256>>>(factor);
    pos_kernel<<<(N * 32 + 255) / 256, 256>>>();
    gram_mma_kernel<<<NCTA, 256, SMEM_BYTES>>>();
    finish_partial_kernel<<<32, 256>>>();
    finish_final_kernel<<<1, 32>>>((float*)d_out);
}

// round 6
// speedup vs baseline: 6.0441x; 1.0245x over previous
#include <cuda_runtime.h>
#include <cuda_fp16.h>
#include <cstdint>
#include <stdint.h>
#include <math.h>

#define N 8192
#define D 128
#define TILE 128
#define NB (N / TILE)             // 64
#define NTRI (NB * (NB + 1) / 2)  // 2080 upper-tri tiles
#define NCTA 296                  // 148 SMs x 2 resident CTAs
#define LDH 136                   // padded SMEM stride (272B): LDSM conflict-free
#define WEIGHT 0.01f

// ---------------------------------------------------------------------------
// Device scratch
// ---------------------------------------------------------------------------
__device__ float  g_f[N * D];
__device__ __half g_fh[N * D];
__device__ float  g_suffix[N];
__device__ float  g_prefix[N];
__device__ float  g_pos[N];
__device__ float  g_partial[32];

// ---------------------------------------------------------------------------
__device__ __forceinline__ void mma16816(float* c,
    uint32_t a0, uint32_t a1, uint32_t a2, uint32_t a3,
    uint32_t b0, uint32_t b1)
{
    asm volatile(
        "mma.sync.aligned.m16n8k16.row.col.f32.f16.f16.f32 "
        "{%0,%1,%2,%3}, {%4,%5,%6,%7}, {%8,%9}, {%0,%1,%2,%3};"
        : "+f"(c[0]), "+f"(c[1]), "+f"(c[2]), "+f"(c[3])
        : "r"(a0), "r"(a1), "r"(a2), "r"(a3), "r"(b0), "r"(b1));
}

__device__ __forceinline__ void ldsm_x4(uint32_t& r0, uint32_t& r1,
                                        uint32_t& r2, uint32_t& r3, uint32_t a) {
    asm volatile("ldmatrix.sync.aligned.m8n8.x4.shared.b16 {%0,%1,%2,%3}, [%4];"
                 : "=r"(r0), "=r"(r1), "=r"(r2), "=r"(r3) : "r"(a));
}
__device__ __forceinline__ void ldsm_x2(uint32_t& r0, uint32_t& r1, uint32_t a) {
    asm volatile("ldmatrix.sync.aligned.m8n8.x2.shared.b16 {%0,%1}, [%2];"
                 : "=r"(r0), "=r"(r1) : "r"(a));
}

__device__ __forceinline__ uint32_t smem_u32(const void* p) {
    uint32_t a;
    asm("{ .reg .u64 t; cvta.to.shared.u64 t, %1; cvt.u32.u64 %0, t; }"
        : "=r"(a) : "l"(p));
    return a;
}

#define CP_COMMIT()  asm volatile("cp.async.commit_group;" ::: "memory")
#define CP_WAIT_ALL() asm volatile("cp.async.wait_all;" ::: "memory")

// 128x128 half tile -> padded SMEM via cp.async (8 x 16B per thread)
__device__ __forceinline__ void prefetch_tile(uint32_t dst_s,
                                              const __half* __restrict__ src,
                                              int tid) {
#pragma unroll
    for (int it = 0; it < 8; it++) {
        int idx = tid + it * 256;
        int row = idx >> 4;
        int ch  = idx & 15;
        uint32_t d = dst_s + (uint32_t)(row * LDH + ch * 8) * 2u;
        const void* s = src + row * D + ch * 8;
        asm volatile("cp.async.cg.shared.global [%0], [%1], 16;"
                     :: "r"(d), "l"(s) : "memory");
    }
}

// ---------------------------------------------------------------------------
// Kernel 1: L2-normalize rows -> fp32 + fp16; zero accumulators.
// ---------------------------------------------------------------------------
__global__ void normalize_kernel(const float* __restrict__ in) {
    int gw   = (blockIdx.x * blockDim.x + threadIdx.x) >> 5;
    int lane = threadIdx.x & 31;
    if (gw >= N) return;
    float4 v = ((const float4*)(in + (size_t)gw * D))[lane];
    float ss = v.x * v.x + v.y * v.y + v.z * v.z + v.w * v.w;
#pragma unroll
    for (int o = 16; o > 0; o >>= 1) ss += __shfl_xor_sync(0xffffffffu, ss, o);
    float scale = 1.0f / fmaxf(sqrtf(ss), 1e-12f);
    float4 o4 = make_float4(v.x * scale, v.y * scale, v.z * scale, v.w * scale);
    ((float4*)(g_f + (size_t)gw * D))[lane] = o4;
    __half2 h0 = __floats2half2_rn(o4.x, o4.y);
    __half2 h1 = __floats2half2_rn(o4.z, o4.w);
    ((__half2*)(g_fh + (size_t)gw * D))[lane * 2 + 0] = h0;
    ((__half2*)(g_fh + (size_t)gw * D))[lane * 2 + 1] = h1;
    if (lane == 0) { g_suffix[gw] = 0.0f; g_prefix[gw] = 0.0f; }
}

// ---------------------------------------------------------------------------
// Kernel 2: exact fp32 pos[r] = <f_r, f_{r+1}>, one warp per r.
// ---------------------------------------------------------------------------
__global__ void pos_kernel() {
    int gw   = (blockIdx.x * blockDim.x + threadIdx.x) >> 5;
    int lane = threadIdx.x & 31;
    if (gw >= N - 1) return;
    float4 a = ((const float4*)(g_f + (size_t)gw * D))[lane];
    float4 b = ((const float4*)(g_f + (size_t)(gw + 1) * D))[lane];
    float d = a.x * b.x + a.y * b.y + a.z * b.z + a.w * b.w;
#pragma unroll
    for (int o = 16; o > 0; o >>= 1) d += __shfl_xor_sync(0xffffffffu, d, o);
    if (lane == 0) g_pos[gw] = d;
}

// ---------------------------------------------------------------------------
// Kernel 3: persistent gram, cp.async double-buffered B, ldmatrix fragments.
// ---------------------------------------------------------------------------
#define SMEM_BYTES (TILE * LDH * 2 + 2 * TILE * LDH * 2 + 2 * TILE * 4) // 105472

__global__ __launch_bounds__(256, 2) void gram_mma_kernel() {
    extern __shared__ char smem[];
    __half* As  = (__half*)smem;                           // [128][LDH]
    __half* Bs0 = As + TILE * LDH;                         // buf 0
    __half* Bs1 = Bs0 + TILE * LDH;                        // buf 1
    float*  s_row = (float*)(Bs1 + TILE * LDH);            // [128]
    float*  s_col = s_row + TILE;                          // [128]

    const int tid  = threadIdx.x;
    const int wid  = tid >> 5;
    const int lane = tid & 31;
    const int wrow = wid >> 2;        // 0..1
    const int wcol = wid & 3;         // 0..3
    const int g    = lane >> 2;       // 0..7
    const int tg   = lane & 3;        // 0..3

    const uint32_t As_s  = smem_u32(As);
    const uint32_t Bs_s0 = smem_u32(Bs0);
    const uint32_t Bs_s1 = smem_u32(Bs1);

    // LDSM lane-address offsets (bytes) within a tile
    const uint32_t aoff = (uint32_t)((lane & 15) * LDH + (lane >> 4) * 8) * 2u;
    const uint32_t boff = (uint32_t)((lane & 7) * LDH + ((lane >> 3) & 1) * 8) * 2u;

    const int lo = (int)(((long long)blockIdx.x * NTRI) / NCTA);
    const int hi = (int)(((long long)(blockIdx.x + 1) * NTRI) / NCTA);

    int I = 0;
    while ((I + 1) * NB - (I + 1) * I / 2 <= lo) ++I;
    {
        const int J0 = I + (lo - (I * NB - I * (I - 1) / 2));
        prefetch_tile(As_s, g_fh + (size_t)I * TILE * D, tid);
        prefetch_tile(Bs_s0, g_fh + (size_t)J0 * TILE * D, tid);
        CP_COMMIT();
    }

    int buf = 0;
    for (int t = lo; t < hi; ++t) {
        while ((I + 1) * NB - (I + 1) * I / 2 <= t) ++I;
        const int J = I + (t - (I * NB - I * (I - 1) / 2));

        // next-tile indices
        int In = I, Jn = 0;
        const bool have_next = (t + 1 < hi);
        if (have_next) {
            while ((In + 1) * NB - (In + 1) * In / 2 <= t + 1) ++In;
            Jn = In + ((t + 1) - (In * NB - In * (In - 1) / 2));
        }

        CP_WAIT_ALL();
        __syncthreads();          // tiles ready; prev iter's s_row reads done

        if (tid < TILE) s_row[tid] = 0.0f;
        else            s_col[tid - TILE] = 0.0f;

        // prefetch next B into the other buffer while we compute
        if (have_next)
            prefetch_tile(buf ? Bs_s0 : Bs_s1, g_fh + (size_t)Jn * TILE * D, tid);
        CP_COMMIT();
        __syncthreads();          // zeroed staging visible to all warps

        const uint32_t Acur = As_s + aoff;
        const uint32_t Bcur = (buf ? Bs_s1 : Bs_s0) + boff;

        float acc[4][4][4];
#pragma unroll
        for (int mt = 0; mt < 4; mt++)
#pragma unroll
            for (int nt = 0; nt < 4; nt++)
#pragma unroll
                for (int e = 0; e < 4; e++) acc[mt][nt][e] = 0.0f;

#pragma unroll
        for (int k0 = 0; k0 < D; k0 += 16) {
            uint32_t bfr[4][2];
#pragma unroll
            for (int nt = 0; nt < 4; nt++)
                ldsm_x2(bfr[nt][0], bfr[nt][1],
                        Bcur + (uint32_t)((wcol * 32 + nt * 8) * LDH + k0) * 2u);
#pragma unroll
            for (int mt = 0; mt < 4; mt++) {
                uint32_t a0, a1, a2, a3;
                ldsm_x4(a0, a1, a2, a3,
                        Acur + (uint32_t)((wrow * 64 + mt * 16) * LDH + k0) * 2u);
#pragma unroll
                for (int nt = 0; nt < 4; nt++)
                    mma16816(acc[mt][nt], a0, a1, a2, a3, bfr[nt][0], bfr[nt][1]);
            }
        }

        // --- Epilogue: masked exp + reductions ---
        float csum[4][2];
#pragma unroll
        for (int nt = 0; nt < 4; nt++) { csum[nt][0] = 0.0f; csum[nt][1] = 0.0f; }

#pragma unroll
        for (int mt = 0; mt < 4; mt++) {
            const int gi0 = I * TILE + wrow * 64 + mt * 16 + g;
            const int gi1 = gi0 + 8;
            float rs0 = 0.0f, rs1 = 0.0f;
#pragma unroll
            for (int nt = 0; nt < 4; nt++) {
                const int gj0 = J * TILE + wcol * 32 + nt * 8 + tg * 2;
                const int gj1 = gj0 + 1;
                float e00 = (gj0 > gi0) ? __expf(acc[mt][nt][0]) : 0.0f;
                float e01 = (gj1 > gi0) ? __expf(acc[mt][nt][1]) : 0.0f;
                float e10 = (gj0 > gi1) ? __expf(acc[mt][nt][2]) : 0.0f;
                float e11 = (gj1 > gi1) ? __expf(acc[mt][nt][3]) : 0.0f;
                rs0 += e00 + e01;
                rs1 += e10 + e11;
                csum[nt][0] += ((gj0 >= gi0 + 2) ? e00 : 0.0f) + ((gj0 >= gi1 + 2) ? e10 : 0.0f);
                csum[nt][1] += ((gj1 >= gi0 + 2) ? e01 : 0.0f) + ((gj1 >= gi1 + 2) ? e11 : 0.0f);
            }
            rs0 += __shfl_xor_sync(0xffffffffu, rs0, 1);
            rs0 += __shfl_xor_sync(0xffffffffu, rs0, 2);
            rs1 += __shfl_xor_sync(0xffffffffu, rs1, 1);
            rs1 += __shfl_xor_sync(0xffffffffu, rs1, 2);
            if (tg == 0) {
                atomicAdd(&s_row[wrow * 64 + mt * 16 + g], rs0);
                atomicAdd(&s_row[wrow * 64 + mt * 16 + g + 8], rs1);
            }
        }

#pragma unroll
        for (int nt = 0; nt < 4; nt++) {
#pragma unroll
            for (int e = 0; e < 2; e++) {
                float v = csum[nt][e];
                v += __shfl_xor_sync(0xffffffffu, v, 4);
                v += __shfl_xor_sync(0xffffffffu, v, 8);
                v += __shfl_xor_sync(0xffffffffu, v, 16);
                if (g == 0) atomicAdd(&s_col[wcol * 32 + nt * 8 + tg * 2 + e], v);
            }
        }

        __syncthreads();          // all warps past mainloop + staging complete

        // A changes next tile: safe to overwrite As now
        if (have_next && In != I) {
            prefetch_tile(As_s, g_fh + (size_t)In * TILE * D, tid);
            CP_COMMIT();
        }

        if (tid < TILE) atomicAdd(&g_suffix[I * TILE + tid], s_row[tid]);
        else            atomicAdd(&g_prefix[J * TILE + tid - TILE], s_col[tid - TILE]);

        buf ^= 1;
    }
}

// ---------------------------------------------------------------------------
// Kernel 4a: parallel partials of (lse - pos).
// ---------------------------------------------------------------------------
__global__ void finish_partial_kernel() {
    __shared__ float red[256];
    int t = threadIdx.x;
    int r = blockIdx.x * 256 + t;
    float local = 0.0f;
    if (r < N - 1)
        local = logf(g_suffix[r] + g_prefix[r + 1]) - g_pos[r];
    red[t] = local;
    __syncthreads();
    for (int s = 128; s > 0; s >>= 1) {
        if (t < s) red[t] += red[t + s];
        __syncthreads();
    }
    if (t == 0) g_partial[blockIdx.x] = red[0];
}

__global__ void finish_final_kernel(float* __restrict__ out) {
    int t = threadIdx.x;
    float v = g_partial[t];
#pragma unroll
    for (int o = 16; o > 0; o >>= 1) v += __shfl_xor_sync(0xffffffffu, v, o);
    if (t == 0) out[0] = -WEIGHT * (v / (float)N);
}

// ---------------------------------------------------------------------------
extern "C" void kernel_launch(void* const* d_in, const int* in_sizes, int n_in,
                              void* d_out, int out_size) {
    const float* factor = (const float*)d_in[0];
    (void)in_sizes; (void)n_in; (void)out_size;

    static bool attr_set = false;
    if (!attr_set) {
        cudaFuncSetAttribute(gram_mma_kernel,
                             cudaFuncAttributeMaxDynamicSharedMemorySize, SMEM_BYTES);
        attr_set = true;
    }

    normalize_kernel<<<(N * 32) / 256, 256>>>(factor);
    pos_kernel<<<(N * 32 + 255) / 256, 256>>>();
    gram_mma_kernel<<<NCTA, 256, SMEM_BYTES>>>();
    finish_partial_kernel<<<32, 256>>>();
    finish_final_kernel<<<1, 32>>>((float*)d_out);
}

// round 7
// speedup vs baseline: 6.4562x; 1.0682x over previous
#include <cuda_runtime.h>
#include <cuda_fp16.h>
#include <cstdint>
#include <stdint.h>
#include <math.h>

#define N 8192
#define D 128
#define TILE 128
#define NB (N / TILE)             // 64
#define NTRI (NB * (NB + 1) / 2)  // 2080 upper-tri tiles
#define NCTA 296                  // 148 SMs x 2 resident CTAs
#define LDH 136                   // padded SMEM stride, LDSM conflict-free
#define WEIGHT 0.01f

// ---------------------------------------------------------------------------
// Device scratch
// ---------------------------------------------------------------------------
__device__ __half g_fh[N * D];    // normalized rows, fp16
__device__ float  g_suffix[N];
__device__ float  g_prefix[N];
__device__ float  g_pos[N];
__device__ float  g_partial[32];

// ---------------------------------------------------------------------------
__device__ __forceinline__ void mma16816(float* c,
    uint32_t a0, uint32_t a1, uint32_t a2, uint32_t a3,
    uint32_t b0, uint32_t b1)
{
    asm volatile(
        "mma.sync.aligned.m16n8k16.row.col.f32.f16.f16.f32 "
        "{%0,%1,%2,%3}, {%4,%5,%6,%7}, {%8,%9}, {%0,%1,%2,%3};"
        : "+f"(c[0]), "+f"(c[1]), "+f"(c[2]), "+f"(c[3])
        : "r"(a0), "r"(a1), "r"(a2), "r"(a3), "r"(b0), "r"(b1));
}

__device__ __forceinline__ void ldsm_x4(uint32_t& r0, uint32_t& r1,
                                        uint32_t& r2, uint32_t& r3, uint32_t a) {
    asm volatile("ldmatrix.sync.aligned.m8n8.x4.shared.b16 {%0,%1,%2,%3}, [%4];"
                 : "=r"(r0), "=r"(r1), "=r"(r2), "=r"(r3) : "r"(a));
}
__device__ __forceinline__ void ldsm_x2(uint32_t& r0, uint32_t& r1, uint32_t a) {
    asm volatile("ldmatrix.sync.aligned.m8n8.x2.shared.b16 {%0,%1}, [%2];"
                 : "=r"(r0), "=r"(r1) : "r"(a));
}

__device__ __forceinline__ uint32_t smem_u32(const void* p) {
    uint32_t a;
    asm("{ .reg .u64 t; cvta.to.shared.u64 t, %1; cvt.u32.u64 %0, t; }"
        : "=r"(a) : "l"(p));
    return a;
}

#define CP_COMMIT()   asm volatile("cp.async.commit_group;" ::: "memory")
#define CP_WAIT_ALL() asm volatile("cp.async.wait_all;" ::: "memory")

__device__ __forceinline__ void prefetch_tile(uint32_t dst_s,
                                              const __half* __restrict__ src,
                                              int tid) {
#pragma unroll
    for (int it = 0; it < 8; it++) {
        int idx = tid + it * 256;
        int row = idx >> 4;
        int ch  = idx & 15;
        uint32_t d = dst_s + (uint32_t)(row * LDH + ch * 8) * 2u;
        const void* s = src + row * D + ch * 8;
        asm volatile("cp.async.cg.shared.global [%0], [%1], 16;"
                     :: "r"(d), "l"(s) : "memory");
    }
}

// ---------------------------------------------------------------------------
// Kernel 1: L2-normalize rows -> fp16 only; zero accumulators.
// ---------------------------------------------------------------------------
__global__ void normalize_kernel(const float* __restrict__ in) {
    int gw   = (blockIdx.x * blockDim.x + threadIdx.x) >> 5;
    int lane = threadIdx.x & 31;
    if (gw >= N) return;
    float4 v = ((const float4*)(in + (size_t)gw * D))[lane];
    float ss = v.x * v.x + v.y * v.y + v.z * v.z + v.w * v.w;
#pragma unroll
    for (int o = 16; o > 0; o >>= 1) ss += __shfl_xor_sync(0xffffffffu, ss, o);
    float scale = 1.0f / fmaxf(sqrtf(ss), 1e-12f);
    __half2 h0 = __floats2half2_rn(v.x * scale, v.y * scale);
    __half2 h1 = __floats2half2_rn(v.z * scale, v.w * scale);
    ((__half2*)(g_fh + (size_t)gw * D))[lane * 2 + 0] = h0;
    ((__half2*)(g_fh + (size_t)gw * D))[lane * 2 + 1] = h1;
    if (lane == 0) { g_suffix[gw] = 0.0f; g_prefix[gw] = 0.0f; }
}

// ---------------------------------------------------------------------------
// Kernel 2: persistent gram; epilogue specialized; writes g_pos too.
// ---------------------------------------------------------------------------
#define SMEM_BYTES (TILE * LDH * 2 + 2 * TILE * LDH * 2 + 2 * TILE * 4)

__global__ __launch_bounds__(256, 2) void gram_mma_kernel() {
    extern __shared__ char smem[];
    __half* As  = (__half*)smem;
    __half* Bs0 = As + TILE * LDH;
    __half* Bs1 = Bs0 + TILE * LDH;
    float*  s_row = (float*)(Bs1 + TILE * LDH);
    float*  s_col = s_row + TILE;

    const int tid  = threadIdx.x;
    const int wid  = tid >> 5;
    const int lane = tid & 31;
    const int wrow = wid >> 2;
    const int wcol = wid & 3;
    const int g    = lane >> 2;
    const int tg   = lane & 3;

    const uint32_t As_s  = smem_u32(As);
    const uint32_t Bs_s0 = smem_u32(Bs0);
    const uint32_t Bs_s1 = smem_u32(Bs1);

    const uint32_t aoff = (uint32_t)((lane & 15) * LDH + (lane >> 4) * 8) * 2u;
    const uint32_t boff = (uint32_t)((lane & 7) * LDH + ((lane >> 3) & 1) * 8) * 2u;

    const int lo = (int)(((long long)blockIdx.x * NTRI) / NCTA);
    const int hi = (int)(((long long)(blockIdx.x + 1) * NTRI) / NCTA);

    int I = 0;
    while ((I + 1) * NB - (I + 1) * I / 2 <= lo) ++I;
    {
        const int J0 = I + (lo - (I * NB - I * (I - 1) / 2));
        prefetch_tile(As_s, g_fh + (size_t)I * TILE * D, tid);
        prefetch_tile(Bs_s0, g_fh + (size_t)J0 * TILE * D, tid);
        CP_COMMIT();
    }

    int buf = 0;
    for (int t = lo; t < hi; ++t) {
        while ((I + 1) * NB - (I + 1) * I / 2 <= t) ++I;
        const int J = I + (t - (I * NB - I * (I - 1) / 2));

        int In = I, Jn = 0;
        const bool have_next = (t + 1 < hi);
        if (have_next) {
            while ((In + 1) * NB - (In + 1) * In / 2 <= t + 1) ++In;
            Jn = In + ((t + 1) - (In * NB - In * (In - 1) / 2));
        }

        CP_WAIT_ALL();
        __syncthreads();

        if (tid < TILE) s_row[tid] = 0.0f;
        else            s_col[tid - TILE] = 0.0f;

        if (have_next)
            prefetch_tile(buf ? Bs_s0 : Bs_s1, g_fh + (size_t)Jn * TILE * D, tid);
        CP_COMMIT();
        __syncthreads();

        const uint32_t Acur = As_s + aoff;
        const uint32_t Bcur = (buf ? Bs_s1 : Bs_s0) + boff;

        float acc[4][4][4];
#pragma unroll
        for (int mt = 0; mt < 4; mt++)
#pragma unroll
            for (int nt = 0; nt < 4; nt++)
#pragma unroll
                for (int e = 0; e < 4; e++) acc[mt][nt][e] = 0.0f;

#pragma unroll
        for (int k0 = 0; k0 < D; k0 += 16) {
            uint32_t bfr[4][2];
#pragma unroll
            for (int nt = 0; nt < 4; nt++)
                ldsm_x2(bfr[nt][0], bfr[nt][1],
                        Bcur + (uint32_t)((wcol * 32 + nt * 8) * LDH + k0) * 2u);
#pragma unroll
            for (int mt = 0; mt < 4; mt++) {
                uint32_t a0, a1, a2, a3;
                ldsm_x4(a0, a1, a2, a3,
                        Acur + (uint32_t)((wrow * 64 + mt * 16) * LDH + k0) * 2u);
#pragma unroll
                for (int nt = 0; nt < 4; nt++)
                    mma16816(acc[mt][nt], a0, a1, a2, a3, bfr[nt][0], bfr[nt][1]);
            }
        }

        // --- Epilogue ---
        float csum[4][2];
#pragma unroll
        for (int nt = 0; nt < 4; nt++) { csum[nt][0] = 0.0f; csum[nt][1] = 0.0f; }

        if (J > I + 1) {
            // Fast path: every element is strictly above the super-diagonal.
#pragma unroll
            for (int mt = 0; mt < 4; mt++) {
                float rs0 = 0.0f, rs1 = 0.0f;
#pragma unroll
                for (int nt = 0; nt < 4; nt++) {
                    float e00 = __expf(acc[mt][nt][0]);
                    float e01 = __expf(acc[mt][nt][1]);
                    float e10 = __expf(acc[mt][nt][2]);
                    float e11 = __expf(acc[mt][nt][3]);
                    rs0 += e00 + e01;
                    rs1 += e10 + e11;
                    csum[nt][0] += e00 + e10;
                    csum[nt][1] += e01 + e11;
                }
                rs0 += __shfl_xor_sync(0xffffffffu, rs0, 1);
                rs0 += __shfl_xor_sync(0xffffffffu, rs0, 2);
                rs1 += __shfl_xor_sync(0xffffffffu, rs1, 1);
                rs1 += __shfl_xor_sync(0xffffffffu, rs1, 2);
                if (tg == 0) {
                    atomicAdd(&s_row[wrow * 64 + mt * 16 + g], rs0);
                    atomicAdd(&s_row[wrow * 64 + mt * 16 + g + 8], rs1);
                }
            }
        } else {
            // Masked path (diagonal + super-diagonal tiles); also extracts pos.
#pragma unroll
            for (int mt = 0; mt < 4; mt++) {
                const int gi0 = I * TILE + wrow * 64 + mt * 16 + g;
                const int gi1 = gi0 + 8;
                float rs0 = 0.0f, rs1 = 0.0f;
#pragma unroll
                for (int nt = 0; nt < 4; nt++) {
                    const int gj0 = J * TILE + wcol * 32 + nt * 8 + tg * 2;
                    const int gj1 = gj0 + 1;
                    float e00 = (gj0 > gi0) ? __expf(acc[mt][nt][0]) : 0.0f;
                    float e01 = (gj1 > gi0) ? __expf(acc[mt][nt][1]) : 0.0f;
                    float e10 = (gj0 > gi1) ? __expf(acc[mt][nt][2]) : 0.0f;
                    float e11 = (gj1 > gi1) ? __expf(acc[mt][nt][3]) : 0.0f;
                    rs0 += e00 + e01;
                    rs1 += e10 + e11;
                    csum[nt][0] += ((gj0 >= gi0 + 2) ? e00 : 0.0f) + ((gj0 >= gi1 + 2) ? e10 : 0.0f);
                    csum[nt][1] += ((gj1 >= gi0 + 2) ? e01 : 0.0f) + ((gj1 >= gi1 + 2) ? e11 : 0.0f);
                    if (gj0 == gi0 + 1) g_pos[gi0] = acc[mt][nt][0];
                    if (gj1 == gi0 + 1) g_pos[gi0] = acc[mt][nt][1];
                    if (gj0 == gi1 + 1) g_pos[gi1] = acc[mt][nt][2];
                    if (gj1 == gi1 + 1) g_pos[gi1] = acc[mt][nt][3];
                }
                rs0 += __shfl_xor_sync(0xffffffffu, rs0, 1);
                rs0 += __shfl_xor_sync(0xffffffffu, rs0, 2);
                rs1 += __shfl_xor_sync(0xffffffffu, rs1, 1);
                rs1 += __shfl_xor_sync(0xffffffffu, rs1, 2);
                if (tg == 0) {
                    atomicAdd(&s_row[wrow * 64 + mt * 16 + g], rs0);
                    atomicAdd(&s_row[wrow * 64 + mt * 16 + g + 8], rs1);
                }
            }
        }

#pragma unroll
        for (int nt = 0; nt < 4; nt++) {
#pragma unroll
            for (int e = 0; e < 2; e++) {
                float v = csum[nt][e];
                v += __shfl_xor_sync(0xffffffffu, v, 4);
                v += __shfl_xor_sync(0xffffffffu, v, 8);
                v += __shfl_xor_sync(0xffffffffu, v, 16);
                if (g == 0) atomicAdd(&s_col[wcol * 32 + nt * 8 + tg * 2 + e], v);
            }
        }

        __syncthreads();

        if (have_next && In != I) {
            prefetch_tile(As_s, g_fh + (size_t)In * TILE * D, tid);
            CP_COMMIT();
        }

        if (tid < TILE) atomicAdd(&g_suffix[I * TILE + tid], s_row[tid]);
        else            atomicAdd(&g_prefix[J * TILE + tid - TILE], s_col[tid - TILE]);

        buf ^= 1;
    }
}

// ---------------------------------------------------------------------------
// Kernel 3a/3b: parallel (lse - pos) partials, then fold.
// ---------------------------------------------------------------------------
__global__ void finish_partial_kernel() {
    __shared__ float red[256];
    int t = threadIdx.x;
    int r = blockIdx.x * 256 + t;
    float local = 0.0f;
    if (r < N - 1)
        local = __logf(g_suffix[r] + g_prefix[r + 1]) - g_pos[r];
    red[t] = local;
    __syncthreads();
    for (int s = 128; s > 0; s >>= 1) {
        if (t < s) red[t] += red[t + s];
        __syncthreads();
    }
    if (t == 0) g_partial[blockIdx.x] = red[0];
}

__global__ void finish_final_kernel(float* __restrict__ out) {
    int t = threadIdx.x;
    float v = g_partial[t];
#pragma unroll
    for (int o = 16; o > 0; o >>= 1) v += __shfl_xor_sync(0xffffffffu, v, o);
    if (t == 0) out[0] = -WEIGHT * (v / (float)N);
}

// ---------------------------------------------------------------------------
extern "C" void kernel_launch(void* const* d_in, const int* in_sizes, int n_in,
                              void* d_out, int out_size) {
    const float* factor = (const float*)d_in[0];
    (void)in_sizes; (void)n_in; (void)out_size;

    static bool attr_set = false;
    if (!attr_set) {
        cudaFuncSetAttribute(gram_mma_kernel,
                             cudaFuncAttributeMaxDynamicSharedMemorySize, SMEM_BYTES);
        attr_set = true;
    }

    normalize_kernel<<<(N * 32) / 256, 256>>>(factor);
    gram_mma_kernel<<<NCTA, 256, SMEM_BYTES>>>();
    finish_partial_kernel<<<32, 256>>>();
    finish_final_kernel<<<1, 32>>>((float*)d_out);
}